// round 13
// baseline (speedup 1.0000x reference)
#include <cuda_runtime.h>
#include <cuda_fp16.h>

#define NUM_SEG 512
#define HALF_SEG 256
#define D4 16          // float4 chunks per row (D=64)
#define CPS 16         // chunks per segment
#define TPB 512        // two independent 256-thread halves
#define HWARPS 8       // warps per half
#define CAP 144        // rows cached per chunk (covers seg len <= 2304)

// Device scratch (reset/overwritten every launch -> deterministic).
__device__ float4 g_psum[NUM_SEG * CPS * D4];
__device__ float  g_psq [NUM_SEG * CPS];
__device__ int    g_cnt [NUM_SEG];

__device__ __forceinline__ int lower_bound_i32(const int* __restrict__ a, int n, int v) {
    int lo = 0, hi = n;
    while (lo < hi) {
        int mid = (lo + hi) >> 1;
        if (a[mid] < v) lo = mid + 1; else hi = mid;
    }
    return lo;
}

__device__ __forceinline__ uint2 f4_to_h4(float4 v) {
    __half2 lo = __float22half2_rn(make_float2(v.x, v.y));
    __half2 hi = __float22half2_rn(make_float2(v.z, v.w));
    uint2 r;
    r.x = *(unsigned int*)&lo;
    r.y = *(unsigned int*)&hi;
    return r;
}
__device__ __forceinline__ float4 h4_to_f4(uint2 h) {
    float2 a = __half22float2(*(__half2*)&h.x);
    float2 b = __half22float2(*(__half2*)&h.y);
    return make_float4(a.x, a.y, b.x, b.y);
}

// Named barrier over one 256-thread half (ids 1 and 2; 0 is __syncthreads).
__device__ __forceinline__ void hbar(int h) {
    asm volatile("bar.sync %0, 256;" :: "r"(h + 1) : "memory");
}

__global__ __launch_bounds__(NUM_SEG) void k_init() {
    g_cnt[threadIdx.x] = 0;
}

__global__ __launch_bounds__(TPB, 4) void k_fused(
    const float4* __restrict__ x4,   // [N,16]
    const int* __restrict__ batch,   // [N] sorted int32
    float4* __restrict__ out4,
    int N)
{
    const int bid  = blockIdx.x;     // 0 .. 4095
    const int s0   = bid >> 4;       // 0..255
    const int q    = bid & 15;       // chunk 0..15
    const int tid  = threadIdx.x;
    const int h    = tid >> 8;       // half 0/1
    const int htid = tid & 255;
    const int lane = htid & 31;
    const int hwid = htid >> 5;      // warp within half, 0..7
    const int c4   = htid & (D4 - 1);
    const int rg   = htid >> 4;      // row group 0..15

    const int seg = s0 + h * HALF_SEG;   // half 0 -> s0, half 1 -> s0+256

    __shared__ uint2  sh_x[2][CAP * D4];        // 2 x 18.4 KB fp16 caches
    __shared__ float4 sh_wsum[2][HWARPS * D4];  // 2 x 2 KB
    __shared__ float  sh_wsq[2][HWARPS];
    __shared__ float4 sh_fin[2][CPS * D4];      // 2 x 4 KB finalize staging
    __shared__ float4 sh_mean[2][D4];
    __shared__ float  sh_msq[2][D4];
    __shared__ float  sh_inv[2];
    __shared__ int    sh_b[2][2];

    if (htid == 0)  sh_b[h][0] = lower_bound_i32(batch, N, seg);
    if (htid == 32) sh_b[h][1] = lower_bound_i32(batch, N, seg + 1);
    hbar(h);
    const int lo = sh_b[h][0], len = sh_b[h][1] - sh_b[h][0];
    const int qlo = lo + ((len * q) >> 4);
    const int qhi = lo + ((len * (q + 1)) >> 4);
    const int nrows = qhi - qlo;

    // ---- Phase A: stream-read chunk, accumulate, cache fp16 in smem ----
    const unsigned FULL = 0xffffffffu;
    float4 sum4 = make_float4(0.f, 0.f, 0.f, 0.f);
    float  sq   = 0.f;
#pragma unroll 2
    for (int rr = rg; rr < nrows; rr += 16) {
        float4 v = __ldcs(&x4[(size_t)(qlo + rr) * D4 + c4]);
        sum4.x += v.x; sum4.y += v.y; sum4.z += v.z; sum4.w += v.w;
        sq += v.x * v.x + v.y * v.y + v.z * v.z + v.w * v.w;
        if (rr < CAP) sh_x[h][rr * D4 + c4] = f4_to_h4(v);
    }

    // warp reduce: lane+16 shares c4
    sum4.x += __shfl_down_sync(FULL, sum4.x, 16);
    sum4.y += __shfl_down_sync(FULL, sum4.y, 16);
    sum4.z += __shfl_down_sync(FULL, sum4.z, 16);
    sum4.w += __shfl_down_sync(FULL, sum4.w, 16);
#pragma unroll
    for (int off = 16; off >= 1; off >>= 1)
        sq += __shfl_down_sync(FULL, sq, off);
    if (lane < D4) sh_wsum[h][hwid * D4 + lane] = sum4;
    if (lane == 0) sh_wsq[h][hwid] = sq;
    hbar(h);

    if (htid < D4) {
        float4 t = sh_wsum[h][htid];
#pragma unroll
        for (int w = 1; w < HWARPS; w++) {
            float4 b = sh_wsum[h][w * D4 + htid];
            t.x += b.x; t.y += b.y; t.z += b.z; t.w += b.w;
        }
        g_psum[(seg * CPS + q) * D4 + htid] = t;
    }
    if (htid == 32) {
        float t = 0.f;
#pragma unroll
        for (int w = 0; w < HWARPS; w++) t += sh_wsq[h][w];
        g_psq[seg * CPS + q] = t;
    }
    __threadfence();
    hbar(h);
    if (htid == 0) {
        atomicAdd(&g_cnt[seg], 1);
        while (((volatile int*)g_cnt)[seg] < CPS) __nanosleep(64);
    }
    hbar(h);
    __threadfence();

    // ---- Redundant decentralized finalize (per half, in smem) ----
    sh_fin[h][htid] = __ldcg(&g_psum[seg * (CPS * D4) + htid]);  // 256 slots
    hbar(h);
    const float invc = 1.f / (float)max(len, 1);
    if (htid < D4) {
        float4 t = sh_fin[h][htid];
#pragma unroll
        for (int qq = 1; qq < CPS; qq++) {
            float4 b = sh_fin[h][qq * D4 + htid];
            t.x += b.x; t.y += b.y; t.z += b.z; t.w += b.w;
        }
        float4 m = make_float4(t.x * invc, t.y * invc, t.z * invc, t.w * invc);
        sh_mean[h][htid] = m;
        sh_msq[h][htid] = m.x * m.x + m.y * m.y + m.z * m.z + m.w * m.w;
    }
    hbar(h);
    if (htid == 0) {
        float sq_tot = 0.f, msq = 0.f;
#pragma unroll
        for (int i = 0; i < CPS; i++) sq_tot += __ldcg(&g_psq[seg * CPS + i]);
#pragma unroll
        for (int i = 0; i < D4; i++) msq += sh_msq[h][i];
        // segment_mean(|x-m|^2) = segment_mean(|x|^2) - |m|^2
        float var = sq_tot * invc - msq;
        sh_inv[h] = rsqrtf(var);
    }
    hbar(h);

    // ---- Phase B: apply from smem fp16 cache, streaming fp32 output ----
    const float4 m  = sh_mean[h][c4];
    const float  gi = sh_inv[h];
#pragma unroll 2
    for (int rr = rg; rr < nrows; rr += 16) {
        const size_t idx = (size_t)(qlo + rr) * D4 + c4;
        float4 v;
        if (rr < CAP) v = h4_to_f4(sh_x[h][rr * D4 + c4]);
        else          v = __ldcg(&x4[idx]);   // rare overflow fallback
        float4 o;
        o.x = (v.x - m.x) * gi;
        o.y = (v.y - m.y) * gi;
        o.z = (v.z - m.z) * gi;
        o.w = (v.w - m.w) * gi;
        __stcs(&out4[idx], o);
    }
}

extern "C" void kernel_launch(void* const* d_in, const int* in_sizes, int n_in,
                              void* d_out, int out_size)
{
    const float* x     = (const float*)d_in[0];   // [N, 64]
    const int*   batch = (const int*)d_in[1];     // [N], sorted int32
    float*       out   = (float*)d_out;
    const int N = in_sizes[1];

    k_init<<<1, NUM_SEG>>>();
    k_fused<<<HALF_SEG * CPS, TPB>>>((const float4*)x, batch, (float4*)out, N);
}

// round 15
// speedup vs baseline: 1.1528x; 1.1528x over previous
#include <cuda_runtime.h>
#include <cuda_fp16.h>

#define NUM_SEG 512
#define D4 16          // float4 chunks per row (D=64)
#define CPS 4          // chunks per segment
#define TPB 1024
#define NWARP (TPB / 32)   // 32
#define RGN (TPB / D4)     // 64 row groups
#define CAP 528        // rows cached in smem per chunk (covers seg len <= 2112)

// Device scratch (reset/overwritten every launch -> deterministic).
__device__ float4 g_psum[NUM_SEG * CPS * D4];
__device__ float  g_psq [NUM_SEG * CPS];
__device__ int    g_cnt [NUM_SEG];

__device__ __forceinline__ int lower_bound_i32(const int* __restrict__ a, int n, int v) {
    int lo = 0, hi = n;
    while (lo < hi) {
        int mid = (lo + hi) >> 1;
        if (a[mid] < v) lo = mid + 1; else hi = mid;
    }
    return lo;
}

__device__ __forceinline__ uint2 f4_to_h4(float4 v) {
    __half2 lo = __float22half2_rn(make_float2(v.x, v.y));
    __half2 hi = __float22half2_rn(make_float2(v.z, v.w));
    uint2 r;
    r.x = *(unsigned int*)&lo;
    r.y = *(unsigned int*)&hi;
    return r;
}
__device__ __forceinline__ float4 h4_to_f4(uint2 h) {
    float2 a = __half22float2(*(__half2*)&h.x);
    float2 b = __half22float2(*(__half2*)&h.y);
    return make_float4(a.x, a.y, b.x, b.y);
}

__global__ __launch_bounds__(NUM_SEG) void k_init() {
    g_cnt[threadIdx.x] = 0;
}

__global__ __launch_bounds__(TPB, 2) void k_fused(
    const float4* __restrict__ x4,   // [N,16]
    const int* __restrict__ batch,   // [N] sorted int32
    float4* __restrict__ out4,
    int N)
{
    const int bid = blockIdx.x;      // 0 .. 2047
    const int s   = bid >> 2;        // segment 0..511
    const int q   = bid & 3;         // chunk 0..3
    const int tid = threadIdx.x;
    const int lane = tid & 31;
    const int wid  = tid >> 5;       // 0..31
    const int c4 = tid & (D4 - 1);   // column chunk 0..15
    const int rg = tid >> 4;         // row group 0..63

    __shared__ uint2  sh_x[CAP * D4];          // 67.6 KB fp16 chunk cache
    __shared__ float4 sh_wsum[NWARP * D4];     // 8 KB
    __shared__ float  sh_wsq[NWARP];
    __shared__ float4 sh_fin[CPS * D4];        // 1 KB finalize staging
    __shared__ float4 sh_mean[D4];
    __shared__ float  sh_msq[D4];
    __shared__ float  sh_inv;
    __shared__ int    sh_b[2];

    if (tid == 0)  sh_b[0] = lower_bound_i32(batch, N, s);
    if (tid == 32) sh_b[1] = lower_bound_i32(batch, N, s + 1);
    __syncthreads();
    const int lo = sh_b[0], len = sh_b[1] - sh_b[0];
    const int qlo = lo + ((len * q) >> 2);
    const int qhi = lo + ((len * (q + 1)) >> 2);
    const int nrows = qhi - qlo;

    // ---- Phase A: stream-read chunk, accumulate, cache fp16 in smem ----
    const unsigned FULL = 0xffffffffu;
    float4 sum4 = make_float4(0.f, 0.f, 0.f, 0.f);
    float  sq   = 0.f;
#pragma unroll 2
    for (int rr = rg; rr < nrows; rr += RGN) {
        float4 v = __ldcs(&x4[(size_t)(qlo + rr) * D4 + c4]);
        sum4.x += v.x; sum4.y += v.y; sum4.z += v.z; sum4.w += v.w;
        sq += v.x * v.x + v.y * v.y + v.z * v.z + v.w * v.w;
        if (rr < CAP) sh_x[rr * D4 + c4] = f4_to_h4(v);
    }

    // warp reduce: lane+16 shares c4
    sum4.x += __shfl_down_sync(FULL, sum4.x, 16);
    sum4.y += __shfl_down_sync(FULL, sum4.y, 16);
    sum4.z += __shfl_down_sync(FULL, sum4.z, 16);
    sum4.w += __shfl_down_sync(FULL, sum4.w, 16);
#pragma unroll
    for (int off = 16; off >= 1; off >>= 1)
        sq += __shfl_down_sync(FULL, sq, off);
    if (lane < D4) sh_wsum[wid * D4 + lane] = sum4;
    if (lane == 0) sh_wsq[wid] = sq;
    __syncthreads();

    if (tid < D4) {
        float4 t = sh_wsum[tid];
#pragma unroll
        for (int w = 1; w < NWARP; w++) {
            float4 b = sh_wsum[w * D4 + tid];
            t.x += b.x; t.y += b.y; t.z += b.z; t.w += b.w;
        }
        g_psum[bid * D4 + tid] = t;
    }
    if (tid == 32) {
        float t = 0.f;
#pragma unroll
        for (int w = 0; w < NWARP; w++) t += sh_wsq[w];
        g_psq[bid] = t;
    }
    __threadfence();
    __syncthreads();
    if (tid == 0) {
        atomicAdd(&g_cnt[s], 1);
        while (((volatile int*)g_cnt)[s] < CPS) __nanosleep(64);
    }
    __syncthreads();
    __threadfence();

    // ---- Redundant decentralized finalize (every block, in smem) ----
    if (tid < CPS * D4) {            // 64 threads: qq = tid>>4, c4 = tid&15
        sh_fin[tid] = __ldcg(&g_psum[s * (CPS * D4) + tid]);
    }
    __syncthreads();
    const float invc = 1.f / (float)max(len, 1);
    if (tid < D4) {
        float4 t = sh_fin[tid];
#pragma unroll
        for (int qq = 1; qq < CPS; qq++) {
            float4 b = sh_fin[qq * D4 + tid];
            t.x += b.x; t.y += b.y; t.z += b.z; t.w += b.w;
        }
        float4 m = make_float4(t.x * invc, t.y * invc, t.z * invc, t.w * invc);
        sh_mean[tid] = m;
        sh_msq[tid] = m.x * m.x + m.y * m.y + m.z * m.z + m.w * m.w;
    }
    __syncthreads();
    if (tid == 0) {
        float sq_tot = 0.f, msq = 0.f;
#pragma unroll
        for (int i = 0; i < CPS; i++) sq_tot += __ldcg(&g_psq[s * CPS + i]);
#pragma unroll
        for (int i = 0; i < D4; i++) msq += sh_msq[i];
        // segment_mean(|x-m|^2) = segment_mean(|x|^2) - |m|^2
        float var = sq_tot * invc - msq;
        sh_inv = rsqrtf(var);
    }
    __syncthreads();

    // ---- Phase B: apply from smem fp16 cache, streaming fp32 output ----
    const float4 m  = sh_mean[c4];
    const float  gi = sh_inv;
#pragma unroll 2
    for (int rr = rg; rr < nrows; rr += RGN) {
        const size_t idx = (size_t)(qlo + rr) * D4 + c4;
        float4 v;
        if (rr < CAP) v = h4_to_f4(sh_x[rr * D4 + c4]);
        else          v = __ldcg(&x4[idx]);   // rare overflow fallback
        float4 o;
        o.x = (v.x - m.x) * gi;
        o.y = (v.y - m.y) * gi;
        o.z = (v.z - m.z) * gi;
        o.w = (v.w - m.w) * gi;
        __stcs(&out4[idx], o);
    }
}

extern "C" void kernel_launch(void* const* d_in, const int* in_sizes, int n_in,
                              void* d_out, int out_size)
{
    const float* x     = (const float*)d_in[0];   // [N, 64]
    const int*   batch = (const int*)d_in[1];     // [N], sorted int32
    float*       out   = (float*)d_out;
    const int N = in_sizes[1];

    k_init<<<1, NUM_SEG>>>();
    k_fused<<<NUM_SEG * CPS, TPB>>>((const float4*)x, batch, (float4*)out, N);
}